// round 16
// baseline (speedup 1.0000x reference)
#include <cuda_runtime.h>
#include <cstdint>
#include <cstddef>

// Problem constants
#define BB   8
#define SS   2048
#define NN   8
#define HH   1024
#define DD   64
#define TEMP 50.0f
#define CH   64      // S-chunks for pooling
#define SCH  32      // S per chunk (CH*SCH == SS)

// ---------------- device scratch (allocation-free: __device__ globals) -----
__device__ float g_qpart[BB][CH][HH];
__device__ float g_kpart[BB][CH][NN * DD];
__device__ float g_lenpart[BB][CH];
__device__ float g_qenc[BB][DD];
__device__ float g_kenc[BB][NN * DD];
__device__ float g_vmix[(size_t)BB * SS * HH];   // 64 MB, tf32-rounded fp32
__device__ float g_wvr[HH * HH];                 // 4 MB, tf32-rounded Wv

__device__ __forceinline__ float tf32_rna(float x) {
    uint32_t u;
    asm("cvt.rna.tf32.f32 %0, %1;" : "=r"(u) : "f"(x));
    return __uint_as_float(u);
}

__device__ __forceinline__ float warp_sum(float v) {
    #pragma unroll
    for (int o = 16; o > 0; o >>= 1) v += __shfl_xor_sync(0xFFFFFFFFu, v, o);
    return v;
}

// PDL: wait until the programmatically-depended-on producer kernel's memory
// is visible. No-op if launched without the PDL attribute.
__device__ __forceinline__ void pdl_wait() {
    asm volatile("griddepcontrol.wait;" ::: "memory");
}

// ---------------- 1) masked-pool partials + Wv tf32 rounding (fused grid) ---
__global__ void k_pool_round(const float* __restrict__ query,
                             const float* __restrict__ key,
                             const int* __restrict__ amask,
                             const float* __restrict__ Wv) {
    const int blk = blockIdx.x;
    const int tid = threadIdx.x;
    if (blk >= BB * CH) {
        const int i = (blk - BB * CH) * 256 + tid;   // float4 index, 262144 total
        float4 v = ((const float4*)Wv)[i];
        v.x = tf32_rna(v.x); v.y = tf32_rna(v.y);
        v.z = tf32_rna(v.z); v.w = tf32_rna(v.w);
        ((float4*)g_wvr)[i] = v;
        return;
    }
    const int b = blk >> 6, c = blk & 63;
    const int s0 = c * SCH;
    __shared__ float sm[SCH];
    if (tid < SCH)
        sm[tid] = (amask[b * SS + s0 + tid] == 0) ? 1.0f : 0.0f;
    __syncthreads();
    if (tid == 0) {
        float l = 0.f;
        #pragma unroll
        for (int s = 0; s < SCH; s++) l += sm[s];
        g_lenpart[b][c] = l;
    }
    float aqA[4] = {0.f, 0.f, 0.f, 0.f}, aqB[4] = {0.f, 0.f, 0.f, 0.f};
    float akA[2] = {0.f, 0.f},           akB[2] = {0.f, 0.f};
    #pragma unroll 1
    for (int s = 0; s < SCH; s += 2) {
        const float m0 = sm[s], m1 = sm[s + 1];
        const float* qr0 = query + (size_t)(b * SS + s0 + s) * HH;
        const float* qr1 = qr0 + HH;
        const float* kr0 = key + (size_t)(b * SS + s0 + s) * (NN * DD);
        const float* kr1 = kr0 + NN * DD;
        #pragma unroll
        for (int j = 0; j < 4; j++) {
            aqA[j] += m0 * __ldcs(qr0 + tid + j * 256);
            aqB[j] += m1 * __ldcs(qr1 + tid + j * 256);
        }
        #pragma unroll
        for (int j = 0; j < 2; j++) {
            akA[j] += m0 * __ldcs(kr0 + tid + j * 256);
            akB[j] += m1 * __ldcs(kr1 + tid + j * 256);
        }
    }
    #pragma unroll
    for (int j = 0; j < 4; j++) g_qpart[b][c][tid + j * 256] = aqA[j] + aqB[j];
    #pragma unroll
    for (int j = 0; j < 2; j++) g_kpart[b][c][tid + j * 256] = akA[j] + akB[j];
}

// ---------------- 2) combine + encoders (16 blocks; per-b combine ONCE) -----
__global__ void k_cenc(const float* __restrict__ Wq,
                       const float* __restrict__ bq,
                       const float* __restrict__ Wk,
                       const float* __restrict__ bk) {
    __shared__ float s_pool[HH];       // pooled sums (unscaled)
    __shared__ float s_inv;
    const int blk = blockIdx.x;
    const int tid = threadIdx.x;
    const int w = tid >> 5, lane = tid & 31;

    pdl_wait();                        // g_qpart/g_kpart/g_lenpart from pool

    if (blk < BB) {
        const int b = blk;
        if (tid == 0) {
            float l = 0.f;
            #pragma unroll
            for (int c = 0; c < CH; c++) l += g_lenpart[b][c];
            s_inv = 1.0f / l;
        }
        #pragma unroll
        for (int j = 0; j < 4; j++) {
            const int col = tid + j * 256;
            float s = 0.f;
            #pragma unroll 4
            for (int c = 0; c < CH; c++) s += g_qpart[b][c][col];
            s_pool[col] = s;
        }
        __syncthreads();
        const float inv = s_inv;
        #pragma unroll 1
        for (int i = 0; i < 8; i++) {          // 8 warps x 8 dots = 64
            const int dd = w * 8 + i;
            const float* wq = Wq + (size_t)dd * HH;
            float a = 0.f;
            #pragma unroll
            for (int j = 0; j < HH / 32; j++) {
                const int h = lane + j * 32;
                a += s_pool[h] * wq[h];
            }
            a = warp_sum(a);
            if (lane == 0) g_qenc[b][dd] = a * inv + bq[dd];
        }
    } else {
        const int b = blk - BB;
        if (tid == 0) {
            float l = 0.f;
            #pragma unroll
            for (int c = 0; c < CH; c++) l += g_lenpart[b][c];
            s_inv = 1.0f / l;
        }
        #pragma unroll
        for (int j = 0; j < 2; j++) {
            const int col = tid + j * 256;
            float s = 0.f;
            #pragma unroll 4
            for (int c = 0; c < CH; c++) s += g_kpart[b][c][col];
            s_pool[col] = s;
        }
        __syncthreads();
        const float inv = s_inv;
        #pragma unroll 1
        for (int i = 0; i < 64; i++) {         // 8 warps x 64 dots = 512
            const int d0 = w * 64 + i;
            const int n = d0 >> 6, dd = d0 & 63;
            const float* ks = &s_pool[n * DD];
            const float* wk = Wk + dd * DD;
            float a = ks[lane] * wk[lane] + ks[lane + 32] * wk[lane + 32];
            a = warp_sum(a);
            if (lane == 0) g_kenc[b][n * DD + dd] = a * inv + bk[dd];
        }
    }
}

// ---------------- 3) vmix (+ inline softmax), persistent grid-strided -------
#define VGRID 740
__global__ void k_vmix(const float* __restrict__ value) {
    const int tid = threadIdx.x;             // 256 threads: one float4 col each
    __shared__ float sp[NN];
    __shared__ float ssc[NN];
    pdl_wait();                              // g_qenc/g_kenc from cenc
    #pragma unroll 1
    for (int t = blockIdx.x; t < 2048; t += VGRID) {
        const int r0 = t * 8;
        const int b = t >> 8;                // 256 tasks per batch
        if (tid < NN) {
            float a = 0.f;
            const float* ke = &g_kenc[b][tid * DD];
            const float* qe = g_qenc[b];
            #pragma unroll
            for (int d = 0; d < DD; d++) a += ke[d] * qe[d];
            ssc[tid] = a * (1.0f / TEMP);
        }
        __syncthreads();
        if (tid == 0) {
            float mx = -1e30f;
            #pragma unroll
            for (int n = 0; n < NN; n++) mx = fmaxf(mx, ssc[n]);
            float e[NN], sum = 0.f;
            #pragma unroll
            for (int n = 0; n < NN; n++) { e[n] = expf(ssc[n] - mx); sum += e[n]; }
            const float isum = 1.0f / sum;
            #pragma unroll
            for (int n = 0; n < NN; n++) sp[n] = e[n] * isum;
        }
        __syncthreads();
        #pragma unroll
        for (int rp = 0; rp < 4; rp++) {
            const size_t row0 = (size_t)(r0 + rp * 2);
            const size_t row1 = row0 + 1;
            const float4* vp0 = (const float4*)(value + row0 * (NN * HH));
            const float4* vp1 = (const float4*)(value + row1 * (NN * HH));
            float4 a0 = make_float4(0.f, 0.f, 0.f, 0.f);
            float4 a1 = make_float4(0.f, 0.f, 0.f, 0.f);
            #pragma unroll
            for (int n = 0; n < NN; n++) {
                const float p = sp[n];
                const float4 v0 = __ldcs(vp0 + n * (HH / 4) + tid);
                const float4 v1 = __ldcs(vp1 + n * (HH / 4) + tid);
                a0.x += p * v0.x; a0.y += p * v0.y; a0.z += p * v0.z; a0.w += p * v0.w;
                a1.x += p * v1.x; a1.y += p * v1.y; a1.z += p * v1.z; a1.w += p * v1.w;
            }
            a0.x = tf32_rna(a0.x); a0.y = tf32_rna(a0.y); a0.z = tf32_rna(a0.z); a0.w = tf32_rna(a0.w);
            a1.x = tf32_rna(a1.x); a1.y = tf32_rna(a1.y); a1.z = tf32_rna(a1.z); a1.w = tf32_rna(a1.w);
            ((float4*)g_vmix)[row0 * (HH / 4) + tid] = a0;
            ((float4*)g_vmix)[row1 * (HH / 4) + tid] = a1;
        }
        __syncthreads();   // sp/ssc reuse safety before next task
    }
}

// ---------------- 4) GEMM: out = vmix @ Wv^T + bv (tf32 mma.sync) -----------
// Proven R8 kernel; PDL variant: B-tile cp.async issued BEFORE the producer
// wait (B = g_wvr doesn't depend on vmix), A-tile after.
#define BM 128
#define BN 128
#define BK 32
#define LDA 36                 // padded smem stride: bank = 4*grp+qid, conflict-free
#define KT (HH / BK)           // 32
#define NST 3
#define STG_A (BM * LDA)
#define STG_B (BN * LDA)
#define GSMEM (NST * (STG_A + STG_B) * 4)   // 110592 bytes

__device__ __forceinline__ void cp_async16(uint32_t s, const void* g) {
    asm volatile("cp.async.cg.shared.global [%0], [%1], 16;" :: "r"(s), "l"(g));
}

__global__ __launch_bounds__(256, 2) void k_gemm(const float* __restrict__ bias,
                                                 float* __restrict__ C) {
    extern __shared__ float smemf[];
    float* As = smemf;                  // [NST][STG_A]
    float* Bs = smemf + NST * STG_A;    // [NST][STG_B]
    const int tid = threadIdx.x;
    const int m0 = blockIdx.y * BM, n0 = blockIdx.x * BN;
    const int warp = tid >> 5, lane = tid & 31;
    const int wm = warp >> 2, wn = warp & 3;    // 2 x 4 warp grid
    const int grp = lane >> 2, qid = lane & 3;

    const int ldr = tid >> 3;            // 0..31
    const int ldc = (tid & 7) * 4;       // 0,4,...,28
    const float* Ag = g_vmix + (size_t)(m0 + ldr) * HH + ldc;
    const float* Bg = g_wvr + (size_t)(n0 + ldr) * HH + ldc;
    const uint32_t sa = (uint32_t)__cvta_generic_to_shared(&As[ldr * LDA + ldc]);
    const uint32_t sb = (uint32_t)__cvta_generic_to_shared(&Bs[ldr * LDA + ldc]);
    const uint32_t stA = sizeof(float) * STG_A;
    const uint32_t stB = sizeof(float) * STG_B;

    float acc[4][4][4];
    #pragma unroll
    for (int i = 0; i < 4; i++)
        #pragma unroll
        for (int j = 0; j < 4; j++)
            #pragma unroll
            for (int v = 0; v < 4; v++) acc[i][j][v] = 0.f;

    // prologue part 1: B tiles for stages 0,1 — independent of vmix producer
    #pragma unroll
    for (int s = 0; s < 2; s++) {
        const int kb = s * BK;
        #pragma unroll
        for (int k = 0; k < 4; k++)
            cp_async16(sb + s * stB + k * 32 * LDA * 4, Bg + (size_t)k * 32 * HH + kb);
    }
    // wait for vmix completion before any g_vmix access
    pdl_wait();
    // prologue part 2: A tiles; commits give group0 = B0+B1+A0, group1 = A1,
    // preserving the mainloop's wait_group 1 contract (stage s ready when
    // <=1 younger groups pending).
    #pragma unroll
    for (int s = 0; s < 2; s++) {
        const int kb = s * BK;
        #pragma unroll
        for (int k = 0; k < 4; k++)
            cp_async16(sa + s * stA + k * 32 * LDA * 4, Ag + (size_t)k * 32 * HH + kb);
        asm volatile("cp.async.commit_group;");
    }

    #pragma unroll 1
    for (int kt = 0; kt < KT; kt++) {
        const int st = kt % NST;
        asm volatile("cp.async.wait_group 1;");
        __syncthreads();   // stage (kt+2)%NST was consumed at iter kt-1 by all warps

        const int s2 = (kt + 2) % NST;
        const int kb2 = (kt + 2) * BK;
        const bool do_pf = (kt + 2 < KT);

        const uint32_t* as = (const uint32_t*)(As + st * STG_A);
        const uint32_t* bs = (const uint32_t*)(Bs + st * STG_B);
        #pragma unroll
        for (int ks = 0; ks < 4; ks++) {
            // interleave next-stage cp.async issue with compute (smooth smem port)
            if (do_pf) {
                cp_async16(sa + s2 * stA + ks * 32 * LDA * 4,
                           Ag + (size_t)ks * 32 * HH + kb2);
                cp_async16(sb + s2 * stB + ks * 32 * LDA * 4,
                           Bg + (size_t)ks * 32 * HH + kb2);
            }
            const int kc = ks * 8 + qid;
            uint32_t af[4][4], bf[4][2];
            #pragma unroll
            for (int mf = 0; mf < 4; mf++) {
                const int r = wm * 64 + mf * 16 + grp;
                af[mf][0] = as[r * LDA + kc];
                af[mf][1] = as[(r + 8) * LDA + kc];
                af[mf][2] = as[r * LDA + kc + 4];
                af[mf][3] = as[(r + 8) * LDA + kc + 4];
            }
            #pragma unroll
            for (int nf = 0; nf < 4; nf++) {
                const int n = wn * 32 + nf * 8 + grp;
                bf[nf][0] = bs[n * LDA + kc];
                bf[nf][1] = bs[n * LDA + kc + 4];
            }
            #pragma unroll
            for (int mf = 0; mf < 4; mf++)
                #pragma unroll
                for (int nf = 0; nf < 4; nf++) {
                    asm volatile(
                        "mma.sync.aligned.m16n8k8.row.col.f32.tf32.tf32.f32 "
                        "{%0,%1,%2,%3}, {%4,%5,%6,%7}, {%8,%9}, {%0,%1,%2,%3};"
                        : "+f"(acc[mf][nf][0]), "+f"(acc[mf][nf][1]),
                          "+f"(acc[mf][nf][2]), "+f"(acc[mf][nf][3])
                        : "r"(af[mf][0]), "r"(af[mf][1]), "r"(af[mf][2]), "r"(af[mf][3]),
                          "r"(bf[nf][0]), "r"(bf[nf][1]));
                }
        }
        asm volatile("cp.async.commit_group;");
    }

    // epilogue: + bias (hoisted per nf), float2 stores
    #pragma unroll
    for (int nf = 0; nf < 4; nf++) {
        const int c = n0 + wn * 32 + nf * 8 + qid * 2;
        const float b0v = __ldg(bias + c);
        const float b1v = __ldg(bias + c + 1);
        #pragma unroll
        for (int mf = 0; mf < 4; mf++) {
            const int r = m0 + wm * 64 + mf * 16 + grp;
            float2 v0 = make_float2(acc[mf][nf][0] + b0v, acc[mf][nf][1] + b1v);
            float2 v1 = make_float2(acc[mf][nf][2] + b0v, acc[mf][nf][3] + b1v);
            *(float2*)(C + (size_t)r * HH + c) = v0;
            *(float2*)(C + (size_t)(r + 8) * HH + c) = v1;
        }
    }
}

// ---------------- launch -----------------------------------------------------
extern "C" void kernel_launch(void* const* d_in, const int* in_sizes, int n_in,
                              void* d_out, int out_size) {
    (void)in_sizes; (void)n_in; (void)out_size;
    const float* query = (const float*)d_in[0];
    const float* key   = (const float*)d_in[1];
    const float* value = (const float*)d_in[2];
    const int*   amask = (const int*)d_in[3];
    const float* Wq    = (const float*)d_in[4];
    const float* bq    = (const float*)d_in[5];
    const float* Wk    = (const float*)d_in[6];
    const float* bk    = (const float*)d_in[7];
    const float* Wv    = (const float*)d_in[8];
    const float* bv    = (const float*)d_in[9];
    float* out = (float*)d_out;

    cudaFuncSetAttribute(k_gemm, cudaFuncAttributeMaxDynamicSharedMemorySize, GSMEM);

    cudaLaunchAttribute pdl_attr[1];
    pdl_attr[0].id = cudaLaunchAttributeProgrammaticStreamSerialization;
    pdl_attr[0].val.programmaticStreamSerializationAllowed = 1;

    k_pool_round<<<BB * CH + HH * HH / (4 * 256), 256>>>(query, key, amask, Wv);

    {   // cenc with PDL
        cudaLaunchConfig_t cfg = {};
        cfg.gridDim = dim3(16);
        cfg.blockDim = dim3(256);
        cfg.dynamicSmemBytes = 0;
        cfg.stream = 0;
        cfg.attrs = pdl_attr;
        cfg.numAttrs = 1;
        cudaLaunchKernelEx(&cfg, k_cenc, Wq, bq, Wk, bk);
    }
    {   // vmix with PDL
        cudaLaunchConfig_t cfg = {};
        cfg.gridDim = dim3(VGRID);
        cfg.blockDim = dim3(256);
        cfg.dynamicSmemBytes = 0;
        cfg.stream = 0;
        cfg.attrs = pdl_attr;
        cfg.numAttrs = 1;
        cudaLaunchKernelEx(&cfg, k_vmix, value);
    }
    {   // gemm with PDL (B-prefetch before producer wait)
        cudaLaunchConfig_t cfg = {};
        cfg.gridDim = dim3(HH / BN, BB * SS / BM);
        cfg.blockDim = dim3(256);
        cfg.dynamicSmemBytes = GSMEM;
        cfg.stream = 0;
        cfg.attrs = pdl_attr;
        cfg.numAttrs = 1;
        cudaLaunchKernelEx(&cfg, k_gemm, (const float*)bv, out);
    }
}

// round 17
// speedup vs baseline: 1.0556x; 1.0556x over previous
#include <cuda_runtime.h>
#include <cstdint>
#include <cstddef>

// Problem constants
#define BB   8
#define SS   2048
#define NN   8
#define HH   1024
#define DD   64
#define TEMP 50.0f
#define CH   64      // S-chunks for pooling
#define SCH  32      // S per chunk (CH*SCH == SS)

// ---------------- device scratch (allocation-free: __device__ globals) -----
__device__ float g_qpart[BB][CH][HH];
__device__ float g_kpart[BB][CH][NN * DD];
__device__ float g_lenpart[BB][CH];
__device__ float g_qsent[BB][HH];
__device__ float g_ksent[BB][NN * DD];
__device__ float g_qenc[BB][DD];
__device__ float g_kenc[BB][NN * DD];
__device__ float g_vmix[(size_t)BB * SS * HH];   // 64 MB, tf32-rounded fp32
__device__ float g_wvr[HH * HH];                 // 4 MB, tf32-rounded Wv

__device__ __forceinline__ float tf32_rna(float x) {
    uint32_t u;
    asm("cvt.rna.tf32.f32 %0, %1;" : "=r"(u) : "f"(x));
    return __uint_as_float(u);
}

__device__ __forceinline__ float warp_sum(float v) {
    #pragma unroll
    for (int o = 16; o > 0; o >>= 1) v += __shfl_xor_sync(0xFFFFFFFFu, v, o);
    return v;
}

// ---------------- 1) masked-pool partials + Wv tf32 rounding (fused grid) ---
__global__ void k_pool_round(const float* __restrict__ query,
                             const float* __restrict__ key,
                             const int* __restrict__ amask,
                             const float* __restrict__ Wv) {
    const int blk = blockIdx.x;
    const int tid = threadIdx.x;
    if (blk >= BB * CH) {
        const int i = (blk - BB * CH) * 256 + tid;   // float4 index, 262144 total
        float4 v = ((const float4*)Wv)[i];
        v.x = tf32_rna(v.x); v.y = tf32_rna(v.y);
        v.z = tf32_rna(v.z); v.w = tf32_rna(v.w);
        ((float4*)g_wvr)[i] = v;
        return;
    }
    const int b = blk >> 6, c = blk & 63;
    const int s0 = c * SCH;
    __shared__ float sm[SCH];
    if (tid < SCH)
        sm[tid] = (amask[b * SS + s0 + tid] == 0) ? 1.0f : 0.0f;
    __syncthreads();
    if (tid == 0) {
        float l = 0.f;
        #pragma unroll
        for (int s = 0; s < SCH; s++) l += sm[s];
        g_lenpart[b][c] = l;
    }
    float aq[4] = {0.f, 0.f, 0.f, 0.f};
    float ak[2] = {0.f, 0.f};
    for (int s = 0; s < SCH; s++) {
        const float m = sm[s];
        const float* qrow = query + (size_t)(b * SS + s0 + s) * HH;
        const float* krow = key   + (size_t)(b * SS + s0 + s) * (NN * DD);
        #pragma unroll
        for (int j = 0; j < 4; j++) aq[j] += m * qrow[tid + j * 256];
        #pragma unroll
        for (int j = 0; j < 2; j++) ak[j] += m * krow[tid + j * 256];
    }
    #pragma unroll
    for (int j = 0; j < 4; j++) g_qpart[b][c][tid + j * 256] = aq[j];
    #pragma unroll
    for (int j = 0; j < 2; j++) g_kpart[b][c][tid + j * 256] = ak[j];
}

// ---------------- 2) combine partials -> pooled means (distributed) --------
__global__ void k_combine() {
    const int tid = blockIdx.x * 256 + threadIdx.x;
    __shared__ float s_inv[BB];
    if (threadIdx.x < BB) {
        float l = 0.f;
        #pragma unroll
        for (int c = 0; c < CH; c++) l += g_lenpart[threadIdx.x][c];
        s_inv[threadIdx.x] = 1.0f / l;
    }
    __syncthreads();
    if (tid < 2048) {            // query columns
        const int b = tid >> 8, c4 = tid & 255;
        float4 a = make_float4(0.f, 0.f, 0.f, 0.f);
        #pragma unroll 4
        for (int c = 0; c < CH; c++) {
            const float4 v = ((const float4*)g_qpart[b][c])[c4];
            a.x += v.x; a.y += v.y; a.z += v.z; a.w += v.w;
        }
        const float inv = s_inv[b];
        a.x *= inv; a.y *= inv; a.z *= inv; a.w *= inv;
        ((float4*)g_qsent[b])[c4] = a;
    } else {                     // key columns
        const int t = tid - 2048;
        const int b = t >> 7, c4 = t & 127;
        float4 a = make_float4(0.f, 0.f, 0.f, 0.f);
        #pragma unroll 4
        for (int c = 0; c < CH; c++) {
            const float4 v = ((const float4*)g_kpart[b][c])[c4];
            a.x += v.x; a.y += v.y; a.z += v.z; a.w += v.w;
        }
        const float inv = s_inv[b];
        a.x *= inv; a.y *= inv; a.z *= inv; a.w *= inv;
        ((float4*)g_ksent[b])[c4] = a;
    }
}

// ---------------- 3) encoders (distributed, warp per dot) -------------------
__global__ void k_enc(const float* __restrict__ Wq,
                      const float* __restrict__ bq,
                      const float* __restrict__ Wk,
                      const float* __restrict__ bk) {
    const int blk = blockIdx.x;
    const int w = threadIdx.x >> 5, lane = threadIdx.x & 31;
    if (blk < 64) {
        const int dot = blk * 8 + w;
        const int b = dot >> 6, dd = dot & 63;
        const float* qs = g_qsent[b];
        const float* wq = Wq + (size_t)dd * HH;
        float a = 0.f;
        #pragma unroll
        for (int j = 0; j < HH / 32; j++) {
            const int h = lane + j * 32;
            a += qs[h] * wq[h];
        }
        a = warp_sum(a);
        if (lane == 0) g_qenc[b][dd] = a + bq[dd];
    } else {
        const int base = (blk - 64) * 256 + w * 32;
        #pragma unroll 1
        for (int i = 0; i < 32; i++) {
            const int dot = base + i;
            const int b = dot >> 9, n = (dot >> 6) & 7, dd = dot & 63;
            const float* ks = &g_ksent[b][n * DD];
            const float* wk = Wk + dd * DD;
            float a = ks[lane] * wk[lane] + ks[lane + 32] * wk[lane + 32];
            a = warp_sum(a);
            if (lane == 0) g_kenc[b][n * DD + dd] = a + bk[dd];
        }
    }
}

// ---------------- 4) vmix (+ inline softmax) --------------------------------
// 16 rows per block, 4 rows interleaved -> 32 independent LDGs in flight.
__global__ void k_vmix(const float* __restrict__ value) {
    const int r0 = blockIdx.x * 16;          // 1024 blocks
    const int b = blockIdx.x >> 7;           // 128 blocks per batch
    const int tid = threadIdx.x;             // 256 threads: one float4 col each
    __shared__ float sp[NN];
    __shared__ float ssc[NN];
    if (tid < NN) {
        float a = 0.f;
        const float* ke = &g_kenc[b][tid * DD];
        const float* qe = g_qenc[b];
        #pragma unroll
        for (int d = 0; d < DD; d++) a += ke[d] * qe[d];
        ssc[tid] = a * (1.0f / TEMP);
    }
    __syncthreads();
    if (tid == 0) {
        float mx = -1e30f;
        #pragma unroll
        for (int n = 0; n < NN; n++) mx = fmaxf(mx, ssc[n]);
        float e[NN], sum = 0.f;
        #pragma unroll
        for (int n = 0; n < NN; n++) { e[n] = expf(ssc[n] - mx); sum += e[n]; }
        const float isum = 1.0f / sum;
        #pragma unroll
        for (int n = 0; n < NN; n++) sp[n] = e[n] * isum;
    }
    __syncthreads();
    #pragma unroll
    for (int rp = 0; rp < 4; rp++) {
        const size_t rb = (size_t)(r0 + rp * 4);
        float4 a0 = make_float4(0.f, 0.f, 0.f, 0.f);
        float4 a1 = a0, a2 = a0, a3 = a0;
        const float4* vp0 = (const float4*)(value + (rb + 0) * (NN * HH));
        const float4* vp1 = (const float4*)(value + (rb + 1) * (NN * HH));
        const float4* vp2 = (const float4*)(value + (rb + 2) * (NN * HH));
        const float4* vp3 = (const float4*)(value + (rb + 3) * (NN * HH));
        #pragma unroll
        for (int n = 0; n < NN; n++) {
            const float p = sp[n];
            const float4 v0 = __ldcs(vp0 + n * (HH / 4) + tid);
            const float4 v1 = __ldcs(vp1 + n * (HH / 4) + tid);
            const float4 v2 = __ldcs(vp2 + n * (HH / 4) + tid);
            const float4 v3 = __ldcs(vp3 + n * (HH / 4) + tid);
            a0.x += p * v0.x; a0.y += p * v0.y; a0.z += p * v0.z; a0.w += p * v0.w;
            a1.x += p * v1.x; a1.y += p * v1.y; a1.z += p * v1.z; a1.w += p * v1.w;
            a2.x += p * v2.x; a2.y += p * v2.y; a2.z += p * v2.z; a2.w += p * v2.w;
            a3.x += p * v3.x; a3.y += p * v3.y; a3.z += p * v3.z; a3.w += p * v3.w;
        }
        a0.x = tf32_rna(a0.x); a0.y = tf32_rna(a0.y); a0.z = tf32_rna(a0.z); a0.w = tf32_rna(a0.w);
        a1.x = tf32_rna(a1.x); a1.y = tf32_rna(a1.y); a1.z = tf32_rna(a1.z); a1.w = tf32_rna(a1.w);
        a2.x = tf32_rna(a2.x); a2.y = tf32_rna(a2.y); a2.z = tf32_rna(a2.z); a2.w = tf32_rna(a2.w);
        a3.x = tf32_rna(a3.x); a3.y = tf32_rna(a3.y); a3.z = tf32_rna(a3.z); a3.w = tf32_rna(a3.w);
        ((float4*)g_vmix)[(rb + 0) * (HH / 4) + tid] = a0;
        ((float4*)g_vmix)[(rb + 1) * (HH / 4) + tid] = a1;
        ((float4*)g_vmix)[(rb + 2) * (HH / 4) + tid] = a2;
        ((float4*)g_vmix)[(rb + 3) * (HH / 4) + tid] = a3;
    }
}

// ---------------- 5) GEMM: out = vmix @ Wv^T + bv (tf32 mma.sync) -----------
// 3-stage cp.async pipeline, BK=32, cp.async issues interleaved with compute.
#define BM 128
#define BN 128
#define BK 32
#define LDA 36                 // padded smem stride: bank = 4*grp+qid, conflict-free
#define KT (HH / BK)           // 32
#define NST 3
#define STG_A (BM * LDA)       // floats per A stage
#define STG_B (BN * LDA)
#define GSMEM (NST * (STG_A + STG_B) * 4)   // 110592 bytes

__device__ __forceinline__ void cp_async16(uint32_t s, const void* g) {
    asm volatile("cp.async.cg.shared.global [%0], [%1], 16;" :: "r"(s), "l"(g));
}

__global__ __launch_bounds__(256, 2) void k_gemm(const float* __restrict__ bias,
                                                 float* __restrict__ C) {
    extern __shared__ float smemf[];
    float* As = smemf;                  // [NST][STG_A]
    float* Bs = smemf + NST * STG_A;    // [NST][STG_B]
    const int tid = threadIdx.x;
    const int m0 = blockIdx.y * BM, n0 = blockIdx.x * BN;
    const int warp = tid >> 5, lane = tid & 31;
    const int wm = warp >> 2, wn = warp & 3;    // 2 x 4 warp grid
    const int grp = lane >> 2, qid = lane & 3;

    // cp.async addressing: rows r = (tid>>3) + 32k (k=0..3), col chunk = tid&7
    const int ldr = tid >> 3;            // 0..31
    const int ldc = (tid & 7) * 4;       // 0,4,...,28
    const float* Ag = g_vmix + (size_t)(m0 + ldr) * HH + ldc;
    const float* Bg = g_wvr + (size_t)(n0 + ldr) * HH + ldc;
    const uint32_t sa = (uint32_t)__cvta_generic_to_shared(&As[ldr * LDA + ldc]);
    const uint32_t sb = (uint32_t)__cvta_generic_to_shared(&Bs[ldr * LDA + ldc]);
    const uint32_t stA = sizeof(float) * STG_A;
    const uint32_t stB = sizeof(float) * STG_B;

    float acc[4][4][4];
    #pragma unroll
    for (int i = 0; i < 4; i++)
        #pragma unroll
        for (int j = 0; j < 4; j++)
            #pragma unroll
            for (int v = 0; v < 4; v++) acc[i][j][v] = 0.f;

    // prologue: stages 0 and 1 in flight
    #pragma unroll
    for (int s = 0; s < 2; s++) {
        const int kb = s * BK;
        #pragma unroll
        for (int k = 0; k < 4; k++) {
            cp_async16(sa + s * stA + k * 32 * LDA * 4, Ag + (size_t)k * 32 * HH + kb);
            cp_async16(sb + s * stB + k * 32 * LDA * 4, Bg + (size_t)k * 32 * HH + kb);
        }
        asm volatile("cp.async.commit_group;");
    }

    #pragma unroll 1
    for (int kt = 0; kt < KT; kt++) {
        const int st = kt % NST;
        asm volatile("cp.async.wait_group 1;");
        __syncthreads();   // stage (kt+2)%NST was consumed at iter kt-1 by all warps

        const int s2 = (kt + 2) % NST;
        const int kb2 = (kt + 2) * BK;
        const bool do_pf = (kt + 2 < KT);

        const uint32_t* as = (const uint32_t*)(As + st * STG_A);
        const uint32_t* bs = (const uint32_t*)(Bs + st * STG_B);
        #pragma unroll
        for (int ks = 0; ks < 4; ks++) {
            // interleave next-stage cp.async issue with compute (smooth smem port)
            if (do_pf) {
                cp_async16(sa + s2 * stA + ks * 32 * LDA * 4,
                           Ag + (size_t)ks * 32 * HH + kb2);
                cp_async16(sb + s2 * stB + ks * 32 * LDA * 4,
                           Bg + (size_t)ks * 32 * HH + kb2);
            }
            const int kc = ks * 8 + qid;
            uint32_t af[4][4], bf[4][2];
            #pragma unroll
            for (int mf = 0; mf < 4; mf++) {
                const int r = wm * 64 + mf * 16 + grp;
                af[mf][0] = as[r * LDA + kc];
                af[mf][1] = as[(r + 8) * LDA + kc];
                af[mf][2] = as[r * LDA + kc + 4];
                af[mf][3] = as[(r + 8) * LDA + kc + 4];
            }
            #pragma unroll
            for (int nf = 0; nf < 4; nf++) {
                const int n = wn * 32 + nf * 8 + grp;
                bf[nf][0] = bs[n * LDA + kc];
                bf[nf][1] = bs[n * LDA + kc + 4];
            }
            #pragma unroll
            for (int mf = 0; mf < 4; mf++)
                #pragma unroll
                for (int nf = 0; nf < 4; nf++) {
                    asm volatile(
                        "mma.sync.aligned.m16n8k8.row.col.f32.tf32.tf32.f32 "
                        "{%0,%1,%2,%3}, {%4,%5,%6,%7}, {%8,%9}, {%0,%1,%2,%3};"
                        : "+f"(acc[mf][nf][0]), "+f"(acc[mf][nf][1]),
                          "+f"(acc[mf][nf][2]), "+f"(acc[mf][nf][3])
                        : "r"(af[mf][0]), "r"(af[mf][1]), "r"(af[mf][2]), "r"(af[mf][3]),
                          "r"(bf[nf][0]), "r"(bf[nf][1]));
                }
        }
        asm volatile("cp.async.commit_group;");
    }

    // epilogue: + bias, float2 stores
    #pragma unroll
    for (int mf = 0; mf < 4; mf++) {
        const int r = m0 + wm * 64 + mf * 16 + grp;
        #pragma unroll
        for (int nf = 0; nf < 4; nf++) {
            const int c = n0 + wn * 32 + nf * 8 + qid * 2;
            const float b0v = __ldg(bias + c);
            const float b1v = __ldg(bias + c + 1);
            float2 v0 = make_float2(acc[mf][nf][0] + b0v, acc[mf][nf][1] + b1v);
            float2 v1 = make_float2(acc[mf][nf][2] + b0v, acc[mf][nf][3] + b1v);
            *(float2*)(C + (size_t)r * HH + c) = v0;
            *(float2*)(C + (size_t)(r + 8) * HH + c) = v1;
        }
    }
}

// ---------------- launch -----------------------------------------------------
extern "C" void kernel_launch(void* const* d_in, const int* in_sizes, int n_in,
                              void* d_out, int out_size) {
    (void)in_sizes; (void)n_in; (void)out_size;
    const float* query = (const float*)d_in[0];
    const float* key   = (const float*)d_in[1];
    const float* value = (const float*)d_in[2];
    const int*   amask = (const int*)d_in[3];
    const float* Wq    = (const float*)d_in[4];
    const float* bq    = (const float*)d_in[5];
    const float* Wk    = (const float*)d_in[6];
    const float* bk    = (const float*)d_in[7];
    const float* Wv    = (const float*)d_in[8];
    const float* bv    = (const float*)d_in[9];
    float* out = (float*)d_out;

    cudaFuncSetAttribute(k_gemm, cudaFuncAttributeMaxDynamicSharedMemorySize, GSMEM);

    k_pool_round<<<BB * CH + HH * HH / (4 * 256), 256>>>(query, key, amask, Wv);
    k_combine<<<12, 256>>>();
    k_enc<<<80, 256>>>(Wq, bq, Wk, bk);
    k_vmix<<<BB * SS / 16, 256>>>(value);
    k_gemm<<<dim3(HH / BN, BB * SS / BM), 256, GSMEM>>>(bv, out);
}